// round 1
// baseline (speedup 1.0000x reference)
#include <cuda_runtime.h>
#include <cuda_bf16.h>
#include <math.h>

// ---------------- problem constants ----------------
#define BB     2
#define TT     16
#define CDIM   128
#define DI     256          // d_inner
#define DS     16           // d_state
#define DTR    8            // dt_rank
#define NPIX   2304         // H*W = 48*48
#define KKEEP  1152         // kept pixels per batch (ratio 0.5)
#define DBL    40           // dt_rank + 2*d_state

// ---------------- device scratch (static, allowed) ----------------
__device__ float g_energy[BB * NPIX];
__device__ int   g_keep  [BB * NPIX];
__device__ int   g_idx   [BB * KKEEP];
__device__ int   g_inv   [BB * NPIX];

__device__ float g_wT_in [CDIM * 2 * DI];   // [c][o]  128 x 512
__device__ float g_wT_out[DI * CDIM];       // [d][c]  256 x 128
__device__ float g_wT_xp [DI * DBL];        // [d][r]  256 x 40
__device__ float g_wT_dt [DTR * DI];        // [r][d]  8 x 256
__device__ float g_wT_m1 [CDIM * CDIM];     // [c][j]
__device__ float g_wT_m2 [CDIM * CDIM];     // [c][j]
__device__ float g_A     [DI * DS];         // -exp(A_log)

__device__ float g_y  [BB * KKEEP * TT * CDIM];  // mamba output rows [bk][t][c]
__device__ float g_xu [BB * TT * KKEEP * CDIM];  // mix output [b][t][k][c]

// ---------------- prep: weight transposes + A ----------------
__global__ void prep_k(const float* __restrict__ in_w,  const float* __restrict__ out_w,
                       const float* __restrict__ xp_w,  const float* __restrict__ dt_w,
                       const float* __restrict__ m1,    const float* __restrict__ m2,
                       const float* __restrict__ A_log) {
    int i = blockIdx.x * blockDim.x + threadIdx.x;
    int stride = gridDim.x * blockDim.x;
    for (int x = i; x < 512 * 128; x += stride) { int o = x / 128, c = x % 128; g_wT_in[c * 512 + o] = in_w[x]; }
    for (int x = i; x < 128 * 256; x += stride) { int c = x / 256, d = x % 256; g_wT_out[d * 128 + c] = out_w[x]; }
    for (int x = i; x < DBL * 256; x += stride) { int r = x / 256, d = x % 256; g_wT_xp[d * DBL + r] = xp_w[x]; }
    for (int x = i; x < 256 * 8;   x += stride) { int d = x / 8,   r = x % 8;   g_wT_dt[r * 256 + d] = dt_w[x]; }
    for (int x = i; x < 128 * 128; x += stride) { int j = x / 128, c = x % 128;
        g_wT_m1[c * 128 + j] = m1[x]; g_wT_m2[c * 128 + j] = m2[x]; }
    for (int x = i; x < 256 * 16;  x += stride) { g_A[x] = -expf(A_log[x]); }
}

// ---------------- energy: mean_t ||x[.,t,:,n]||_2 ----------------
// grid = BB * (NPIX/32) = 144, block 256 = 8 c-groups x 32 n
__global__ void energy_k(const float* __restrict__ x) {
    int b  = blockIdx.x / (NPIX / 32);
    int n0 = (blockIdx.x % (NPIX / 32)) * 32;
    int ni = threadIdx.x & 31, ci = threadIdx.x >> 5;
    __shared__ float sp[8][32];
    float e = 0.f;
    for (int t = 0; t < TT; t++) {
        float p = 0.f;
        for (int c = ci; c < CDIM; c += 8) {
            float v = x[((size_t)((b * TT + t) * CDIM + c)) * NPIX + n0 + ni];
            p += v * v;
        }
        sp[ci][ni] = p;
        __syncthreads();
        if (ci == 0) {
            float s = 0.f;
            #pragma unroll
            for (int q = 0; q < 8; q++) s += sp[q][ni];
            e += sqrtf(s);
        }
        __syncthreads();
    }
    if (ci == 0) g_energy[b * NPIX + n0 + ni] = e * (1.f / (float)TT);
}

// ---------------- rank: top-k membership (JAX tie semantics) ----------------
// grid = BB*NPIX/256 = 18 (each block within a single batch since NPIX%256==0)
__global__ void rank_k() {
    int gid = blockIdx.x * 256 + threadIdx.x;
    int b = gid / NPIX, n = gid % NPIX;
    __shared__ float se[NPIX];
    for (int m = threadIdx.x; m < NPIX; m += 256) se[m] = g_energy[b * NPIX + m];
    __syncthreads();
    float en = se[n];
    int r = 0;
    #pragma unroll 4
    for (int m = 0; m < NPIX; m++) {
        float em = se[m];
        r += (em > en) || (em == en && m < n);
    }
    g_keep[gid] = (r < KKEEP) ? 1 : 0;
}

// ---------------- compact: build sorted idx + inverse map ----------------
// grid = BB, block 256 (NPIX = 256*9)
__global__ void compact_k() {
    int b = blockIdx.x, tid = threadIdx.x;
    __shared__ int soff[257];
    __shared__ int scnt[256];
    int base = tid * 9;
    int kp[9]; int cnt = 0;
    #pragma unroll
    for (int q = 0; q < 9; q++) { kp[q] = g_keep[b * NPIX + base + q]; cnt += kp[q]; }
    scnt[tid] = cnt;
    __syncthreads();
    if (tid == 0) {
        int acc = 0;
        for (int q = 0; q < 256; q++) { soff[q] = acc; acc += scnt[q]; }
        soff[256] = acc;
    }
    __syncthreads();
    int off = soff[tid];
    #pragma unroll
    for (int q = 0; q < 9; q++) {
        int n = base + q;
        if (kp[q]) { g_idx[b * KKEEP + off] = n; g_inv[b * NPIX + n] = off; off++; }
        else        g_inv[b * NPIX + n] = -1;
    }
}

// ---------------- fused mamba: one block per sequence ----------------
// smem: s_x[16*128] | s_xz[16*512] | s_xc[16*256] | s_dbl[16*48] | s_dt[16*256]
// total 19200 floats = 76800 B (dynamic)
__global__ void __launch_bounds__(256) mamba_k(
    const float* __restrict__ x_in,  const float* __restrict__ norm1_w,
    const float* __restrict__ conv_w, const float* __restrict__ conv_b,
    const float* __restrict__ dt_b,   const float* __restrict__ Dp) {
    extern __shared__ float sm[];
    float* s_x   = sm;             // 2048
    float* s_xz  = sm + 2048;      // 8192
    float* s_xc  = sm + 10240;     // 4096
    float* s_dbl = sm + 14336;     // 768
    float* s_dt  = sm + 15104;     // 4096 (also reused as y-buffer)

    int bk = blockIdx.x;
    int b  = bk / KKEEP;
    int n  = g_idx[bk];            // g_idx layout is [b][k] = bk directly
    int tid = threadIdx.x;

    // gather selected pixel's [T, C] slab (scattered reads, L2-resident)
    for (int i = tid; i < TT * CDIM; i += 256) {
        int t = i >> 7, c = i & 127;
        s_x[i] = x_in[((size_t)((b * TT + t) * CDIM + c)) * NPIX + n];
    }
    __syncthreads();

    // rmsnorm1 (warp per 2 rows)
    int wid = tid >> 5, lane = tid & 31;
    for (int t = wid; t < TT; t += 8) {
        float s = 0.f;
        for (int c = lane; c < CDIM; c += 32) { float v = s_x[t * CDIM + c]; s += v * v; }
        #pragma unroll
        for (int o = 16; o; o >>= 1) s += __shfl_xor_sync(0xffffffffu, s, o);
        float sc = rsqrtf(s * (1.f / (float)CDIM) + 1e-5f);
        for (int c = lane; c < CDIM; c += 32) s_x[t * CDIM + c] = s_x[t * CDIM + c] * sc * norm1_w[c];
    }
    __syncthreads();

    // in_proj: xz[16][512] = z @ in_w^T   (register-blocked over t, float4 row broadcasts)
    {
        int o0 = tid * 2;
        float acc0[TT], acc1[TT];
        #pragma unroll
        for (int t = 0; t < TT; t++) { acc0[t] = 0.f; acc1[t] = 0.f; }
        for (int c4 = 0; c4 < CDIM; c4 += 4) {
            float2 wA = *(const float2*)&g_wT_in[(c4 + 0) * 512 + o0];
            float2 wB = *(const float2*)&g_wT_in[(c4 + 1) * 512 + o0];
            float2 wC = *(const float2*)&g_wT_in[(c4 + 2) * 512 + o0];
            float2 wD = *(const float2*)&g_wT_in[(c4 + 3) * 512 + o0];
            #pragma unroll
            for (int t = 0; t < TT; t++) {
                float4 xv = *(const float4*)&s_x[t * CDIM + c4];
                acc0[t] += xv.x * wA.x + xv.y * wB.x + xv.z * wC.x + xv.w * wD.x;
                acc1[t] += xv.x * wA.y + xv.y * wB.y + xv.z * wC.y + xv.w * wD.y;
            }
        }
        #pragma unroll
        for (int t = 0; t < TT; t++) {
            s_xz[t * 512 + o0]     = acc0[t];
            s_xz[t * 512 + o0 + 1] = acc1[t];
        }
    }
    __syncthreads();

    // causal depthwise conv (D_CONV=4) + SiLU  -> s_xc[t][d]
    {
        int d = tid;  // 256 threads == DI
        float w0 = conv_w[d * 4 + 0], w1 = conv_w[d * 4 + 1];
        float w2 = conv_w[d * 4 + 2], w3 = conv_w[d * 4 + 3];
        float cb = conv_b[d];
        #pragma unroll
        for (int t = 0; t < TT; t++) {
            float acc = cb;
            if (t >= 3) acc += w0 * s_xz[(t - 3) * 512 + d];
            if (t >= 2) acc += w1 * s_xz[(t - 2) * 512 + d];
            if (t >= 1) acc += w2 * s_xz[(t - 1) * 512 + d];
            acc += w3 * s_xz[t * 512 + d];
            s_xc[t * DI + d] = acc / (1.f + expf(-acc));
        }
    }
    __syncthreads();

    // x_proj: dbl[16][40] = xc @ xp_w^T
    for (int i = tid; i < TT * DBL; i += 256) {
        int t = i / DBL, r = i % DBL;
        float acc = 0.f;
        #pragma unroll 4
        for (int d = 0; d < DI; d++) acc += s_xc[t * DI + d] * g_wT_xp[d * DBL + r];
        s_dbl[t * 48 + r] = acc;
    }
    __syncthreads();

    // dt = softplus(dt_part @ dt_w^T + dt_b)
    {
        int d = tid;
        float bias = dt_b[d];
        float w[DTR];
        #pragma unroll
        for (int r = 0; r < DTR; r++) w[r] = g_wT_dt[r * DI + d];
        #pragma unroll
        for (int t = 0; t < TT; t++) {
            float acc = bias;
            #pragma unroll
            for (int r = 0; r < DTR; r++) acc += s_dbl[t * 48 + r] * w[r];
            s_dt[t * DI + d] = (acc > 20.f) ? acc : log1pf(expf(acc));
        }
    }
    __syncthreads();

    // selective scan (h[16] per-thread registers) + skip + gating; y overwrites s_dt
    {
        int d = tid;
        float a[DS], h[DS];
        #pragma unroll
        for (int s = 0; s < DS; s++) { a[s] = g_A[d * DS + s]; h[s] = 0.f; }
        float Dd = Dp[d];
        #pragma unroll
        for (int t = 0; t < TT; t++) {
            float dtv = s_dt[t * DI + d];
            float xv  = s_xc[t * DI + d];
            float dtx = dtv * xv;
            float y = 0.f;
            #pragma unroll
            for (int s = 0; s < DS; s++) {
                float dA = __expf(dtv * a[s]);
                h[s] = dA * h[s] + dtx * s_dbl[t * 48 + 8 + s];
                y += h[s] * s_dbl[t * 48 + 24 + s];
            }
            y += xv * Dd;
            float zv = s_xz[t * 512 + DI + d];
            y *= zv / (1.f + expf(-zv));
            s_dt[t * DI + d] = y;   // safe: each thread owns its own element
        }
    }
    __syncthreads();

    // out_proj: [16][128] = y @ out_w^T  -> g_y
    {
        int c = tid & 127, th = tid >> 7;  // 2 t-halves
        int t0 = th * 8;
        float acc[8];
        #pragma unroll
        for (int q = 0; q < 8; q++) acc[q] = 0.f;
        for (int d = 0; d < DI; d++) {
            float w = g_wT_out[d * CDIM + c];
            #pragma unroll
            for (int q = 0; q < 8; q++) acc[q] += s_dt[(t0 + q) * DI + d] * w;
        }
        #pragma unroll
        for (int q = 0; q < 8; q++)
            g_y[((size_t)bk * TT + t0 + q) * CDIM + c] = acc[q];
    }
}

// ---------------- mix: rmsnorm2 + GELU MLP (32 rows per block) ----------------
// smem: s_w[16384] | s_r[4096] | s_h[4096]  = 98304 B (dynamic)
__global__ void __launch_bounds__(128) mix_k(const float* __restrict__ norm2_w,
                                             const float* __restrict__ b1,
                                             const float* __restrict__ b2) {
    extern __shared__ float sm[];
    float* s_w = sm;            // 16384
    float* s_r = sm + 16384;    // 4096
    float* s_h = sm + 20480;    // 4096
    int tid = threadIdx.x;
    int row0 = blockIdx.x * 32;  // global row id = bk*16 + t

    for (int i = tid; i < 32 * CDIM; i += 128) s_r[i] = g_y[(size_t)row0 * CDIM + i];
    for (int i = tid; i < CDIM * CDIM; i += 128) s_w[i] = g_wT_m1[i];
    __syncthreads();

    // rmsnorm2
    int wid = tid >> 5, lane = tid & 31;
    for (int rr = wid; rr < 32; rr += 4) {
        float s = 0.f;
        for (int c = lane; c < CDIM; c += 32) { float v = s_r[rr * CDIM + c]; s += v * v; }
        #pragma unroll
        for (int o = 16; o; o >>= 1) s += __shfl_xor_sync(0xffffffffu, s, o);
        float sc = rsqrtf(s * (1.f / (float)CDIM) + 1e-5f);
        for (int c = lane; c < CDIM; c += 32) s_r[rr * CDIM + c] *= sc * norm2_w[c];
    }
    __syncthreads();

    int jg = tid & 31, rg = tid >> 5;  // 32 j-groups x 4 r-groups
    int j4 = jg * 4, r0 = rg * 8;

    // GEMM1 + gelu(exact)
    {
        float acc[8][4];
        #pragma unroll
        for (int q = 0; q < 8; q++) { acc[q][0]=0; acc[q][1]=0; acc[q][2]=0; acc[q][3]=0; }
        for (int c = 0; c < CDIM; c++) {
            float4 w = *(const float4*)&s_w[c * CDIM + j4];
            #pragma unroll
            for (int q = 0; q < 8; q++) {
                float rv = s_r[(r0 + q) * CDIM + c];
                acc[q][0] += rv * w.x; acc[q][1] += rv * w.y;
                acc[q][2] += rv * w.z; acc[q][3] += rv * w.w;
            }
        }
        float bb0 = b1[j4], bb1 = b1[j4+1], bb2 = b1[j4+2], bb3 = b1[j4+3];
        #pragma unroll
        for (int q = 0; q < 8; q++) {
            float x0 = acc[q][0]+bb0, x1 = acc[q][1]+bb1, x2 = acc[q][2]+bb2, x3 = acc[q][3]+bb3;
            s_h[(r0+q)*CDIM + j4+0] = 0.5f*x0*(1.f+erff(x0*0.7071067811865475f));
            s_h[(r0+q)*CDIM + j4+1] = 0.5f*x1*(1.f+erff(x1*0.7071067811865475f));
            s_h[(r0+q)*CDIM + j4+2] = 0.5f*x2*(1.f+erff(x2*0.7071067811865475f));
            s_h[(r0+q)*CDIM + j4+3] = 0.5f*x3*(1.f+erff(x3*0.7071067811865475f));
        }
    }
    __syncthreads();
    for (int i = tid; i < CDIM * CDIM; i += 128) s_w[i] = g_wT_m2[i];
    __syncthreads();

    // GEMM2 + bias, write xu[b][t][k][c]
    {
        float acc[8][4];
        #pragma unroll
        for (int q = 0; q < 8; q++) { acc[q][0]=0; acc[q][1]=0; acc[q][2]=0; acc[q][3]=0; }
        for (int c = 0; c < CDIM; c++) {
            float4 w = *(const float4*)&s_w[c * CDIM + j4];
            #pragma unroll
            for (int q = 0; q < 8; q++) {
                float rv = s_h[(r0 + q) * CDIM + c];
                acc[q][0] += rv * w.x; acc[q][1] += rv * w.y;
                acc[q][2] += rv * w.z; acc[q][3] += rv * w.w;
            }
        }
        float bb0 = b2[j4], bb1 = b2[j4+1], bb2 = b2[j4+2], bb3 = b2[j4+3];
        #pragma unroll
        for (int q = 0; q < 8; q++) {
            int rid = row0 + r0 + q;
            int b = rid / (KKEEP * TT);
            int rem = rid - b * (KKEEP * TT);
            int k = rem >> 4, t = rem & 15;
            size_t base = (((size_t)(b * TT + t) * KKEEP) + k) * CDIM + j4;
            float4 o;
            o.x = acc[q][0] + bb0; o.y = acc[q][1] + bb1;
            o.z = acc[q][2] + bb2; o.w = acc[q][3] + bb3;
            *(float4*)&g_xu[base] = o;
        }
    }
}

// ---------------- final combine: out = x_in + scatter(xu) ----------------
// float4 over n (fastest dim). grid = 9437184/4/256 = 9216
__global__ void out_k(const float* __restrict__ x_in, float* __restrict__ out) {
    int gid = blockIdx.x * 256 + threadIdx.x;
    size_t base = (size_t)gid * 4;
    int n = (int)(base % NPIX);
    size_t rest = base / NPIX;
    int c = (int)(rest % CDIM); rest /= CDIM;
    int t = (int)(rest % TT);
    int b = (int)(rest / TT);
    float4 v = *(const float4*)&x_in[base];
    int ib = b * NPIX + n;
    int k0 = g_inv[ib], k1 = g_inv[ib + 1], k2 = g_inv[ib + 2], k3 = g_inv[ib + 3];
    size_t xb = ((size_t)(b * TT + t) * KKEEP) * CDIM + c;
    if (k0 >= 0) v.x += g_xu[xb + (size_t)k0 * CDIM];
    if (k1 >= 0) v.y += g_xu[xb + (size_t)k1 * CDIM];
    if (k2 >= 0) v.z += g_xu[xb + (size_t)k2 * CDIM];
    if (k3 >= 0) v.w += g_xu[xb + (size_t)k3 * CDIM];
    *(float4*)&out[base] = v;
}

// ---------------- launch ----------------
extern "C" void kernel_launch(void* const* d_in, const int* in_sizes, int n_in,
                              void* d_out, int out_size) {
    const float* x_in    = (const float*)d_in[0];
    const float* norm1_w = (const float*)d_in[1];
    const float* norm2_w = (const float*)d_in[2];
    const float* in_w    = (const float*)d_in[3];
    const float* conv_w  = (const float*)d_in[4];
    const float* conv_b  = (const float*)d_in[5];
    const float* xp_w    = (const float*)d_in[6];
    const float* dt_w    = (const float*)d_in[7];
    const float* dt_b    = (const float*)d_in[8];
    const float* A_log   = (const float*)d_in[9];
    const float* Dp      = (const float*)d_in[10];
    const float* out_w   = (const float*)d_in[11];
    const float* m1      = (const float*)d_in[12];
    const float* b1      = (const float*)d_in[13];
    const float* m2      = (const float*)d_in[14];
    const float* b2      = (const float*)d_in[15];
    float* out = (float*)d_out;

    cudaFuncSetAttribute(mamba_k, cudaFuncAttributeMaxDynamicSharedMemorySize, 76800);
    cudaFuncSetAttribute(mix_k,   cudaFuncAttributeMaxDynamicSharedMemorySize, 98304);

    prep_k<<<64, 256>>>(in_w, out_w, xp_w, dt_w, m1, m2, A_log);
    energy_k<<<BB * (NPIX / 32), 256>>>(x_in);
    rank_k<<<BB * NPIX / 256, 256>>>();
    compact_k<<<BB, 256>>>();
    mamba_k<<<BB * KKEEP, 256, 76800>>>(x_in, norm1_w, conv_w, conv_b, dt_b, Dp);
    mix_k<<<BB * KKEEP * TT / 32, 128, 98304>>>(norm2_w, b1, b2);
    out_k<<<(BB * TT * CDIM * NPIX) / 4 / 256, 256>>>(x_in, out);
}

// round 4
// speedup vs baseline: 1.7181x; 1.7181x over previous
#include <cuda_runtime.h>
#include <cuda_bf16.h>
#include <math.h>
#include <stdint.h>

// ---------------- problem constants ----------------
#define BB     2
#define TT     16
#define CDIM   128
#define DI     256
#define DS     16
#define DTR    8
#define NPIX   2304
#define KKEEP  1152
#define DBL    40
#define ROWS   (BB * KKEEP * TT)   // 36864 GEMM rows

// ---------------- device scratch ----------------
__device__ float g_energy[BB * NPIX];
__device__ int   g_keep  [BB * NPIX];
__device__ int   g_idx   [BB * KKEEP];
__device__ int   g_inv   [BB * NPIX];

__device__ float g_wT_xp [DI * DBL];
__device__ float g_wT_dt [DTR * DI];
__device__ float g_A     [DI * DS];

__device__ __nv_bfloat16 g_bWin [2 * DI * CDIM];   // [512,128] K-major
__device__ __nv_bfloat16 g_bWout[CDIM * DI];       // [128,256] K-major
__device__ __nv_bfloat16 g_bM1  [CDIM * CDIM];
__device__ __nv_bfloat16 g_bM2  [CDIM * CDIM];

__device__ __nv_bfloat16 g_Xg [ROWS * CDIM];       // normalized input (bf16)
__device__ float         g_xz [ROWS * 2 * DI];     // in_proj out; reused as G2
__device__ __nv_bfloat16 g_ybf[ROWS * DI];         // mamba y (bf16)
__device__ __nv_bfloat16 g_h0 [ROWS * CDIM];       // rmsnorm2 out (bf16)
__device__ __nv_bfloat16 g_h1 [ROWS * CDIM];       // gelu out (bf16)

// ---------------- mma.sync bf16 helper ----------------
__device__ __forceinline__ void mma_bf16(float* c, const uint32_t* a, const uint32_t* b) {
    asm volatile("mma.sync.aligned.m16n8k16.row.col.f32.bf16.bf16.f32 "
                 "{%0,%1,%2,%3}, {%4,%5,%6,%7}, {%8,%9}, {%0,%1,%2,%3};"
                 : "+f"(c[0]), "+f"(c[1]), "+f"(c[2]), "+f"(c[3])
                 : "r"(a[0]), "r"(a[1]), "r"(a[2]), "r"(a[3]), "r"(b[0]), "r"(b[1]));
}

// ---------------- prep ----------------
__global__ void prep_k(const float* __restrict__ in_w,  const float* __restrict__ out_w,
                       const float* __restrict__ xp_w,  const float* __restrict__ dt_w,
                       const float* __restrict__ m1,    const float* __restrict__ m2,
                       const float* __restrict__ A_log) {
    int i = blockIdx.x * blockDim.x + threadIdx.x;
    int stride = gridDim.x * blockDim.x;
    for (int x = i; x < 512 * 128; x += stride) g_bWin[x]  = __float2bfloat16(in_w[x]);
    for (int x = i; x < 128 * 256; x += stride) g_bWout[x] = __float2bfloat16(out_w[x]);
    for (int x = i; x < 128 * 128; x += stride) { g_bM1[x] = __float2bfloat16(m1[x]);
                                                  g_bM2[x] = __float2bfloat16(m2[x]); }
    for (int x = i; x < DBL * 256; x += stride) { int r = x / 256, d = x % 256; g_wT_xp[d * DBL + r] = xp_w[x]; }
    for (int x = i; x < 256 * 8;   x += stride) { int d = x / 8,   r = x % 8;   g_wT_dt[r * 256 + d] = dt_w[x]; }
    for (int x = i; x < 256 * 16;  x += stride) g_A[x] = -expf(A_log[x]);
}

// ---------------- energy ----------------
__global__ void energy_k(const float* __restrict__ x) {
    int b  = blockIdx.x / (NPIX / 32);
    int n0 = (blockIdx.x % (NPIX / 32)) * 32;
    int ni = threadIdx.x & 31, ci = threadIdx.x >> 5;
    __shared__ float sp[8][32];
    float e = 0.f;
    for (int t = 0; t < TT; t++) {
        float p = 0.f;
        for (int c = ci; c < CDIM; c += 8) {
            float v = x[((size_t)((b * TT + t) * CDIM + c)) * NPIX + n0 + ni];
            p += v * v;
        }
        sp[ci][ni] = p;
        __syncthreads();
        if (ci == 0) {
            float s = 0.f;
            #pragma unroll
            for (int q = 0; q < 8; q++) s += sp[q][ni];
            e += sqrtf(s);
        }
        __syncthreads();
    }
    if (ci == 0) g_energy[b * NPIX + n0 + ni] = e * (1.f / (float)TT);
}

// ---------------- rank + compact ----------------
__global__ void rank_k() {
    int gid = blockIdx.x * 256 + threadIdx.x;
    int b = gid / NPIX, n = gid % NPIX;
    __shared__ float se[NPIX];
    for (int m = threadIdx.x; m < NPIX; m += 256) se[m] = g_energy[b * NPIX + m];
    __syncthreads();
    float en = se[n];
    int r = 0;
    #pragma unroll 4
    for (int m = 0; m < NPIX; m++) {
        float em = se[m];
        r += (em > en) || (em == en && m < n);
    }
    g_keep[gid] = (r < KKEEP) ? 1 : 0;
}

__global__ void compact_k() {
    int b = blockIdx.x, tid = threadIdx.x;
    int wid = tid >> 5, lane = tid & 31;
    __shared__ int wsum[8];
    int base = tid * 9;
    int kp[9]; int cnt = 0;
    #pragma unroll
    for (int q = 0; q < 9; q++) { kp[q] = g_keep[b * NPIX + base + q]; cnt += kp[q]; }
    // warp inclusive scan
    int incl = cnt;
    #pragma unroll
    for (int o = 1; o < 32; o <<= 1) {
        int v = __shfl_up_sync(0xffffffffu, incl, o);
        if (lane >= o) incl += v;
    }
    if (lane == 31) wsum[wid] = incl;
    __syncthreads();
    if (tid < 8) {
        int v = wsum[tid];
        int s = v;
        #pragma unroll
        for (int o = 1; o < 8; o <<= 1) {
            int u = __shfl_up_sync(0xffu, s, o);
            if (tid >= o) s += u;
        }
        wsum[tid] = s - v;   // exclusive warp base
    }
    __syncthreads();
    int off = wsum[wid] + incl - cnt;
    #pragma unroll
    for (int q = 0; q < 9; q++) {
        int n = base + q;
        if (kp[q]) { g_idx[b * KKEEP + off] = n; g_inv[b * NPIX + n] = off; off++; }
        else        g_inv[b * NPIX + n] = -1;
    }
}

// ---------------- gather + rmsnorm1 -> bf16 rows ----------------
__global__ void __launch_bounds__(128) gather_norm_k(const float* __restrict__ x_in,
                                                     const float* __restrict__ n1w) {
    __shared__ float s_x[TT * CDIM];
    __shared__ float s_sc[TT];
    int bk = blockIdx.x;
    int b  = bk / KKEEP;
    int n  = g_idx[bk];
    int tid = threadIdx.x;
    for (int t = 0; t < TT; t++)
        s_x[t * CDIM + tid] = x_in[((size_t)((b * TT + t) * CDIM + tid)) * NPIX + n];
    __syncthreads();
    int wid = tid >> 5, lane = tid & 31;
    for (int t = wid; t < TT; t += 4) {
        float s = 0.f;
        #pragma unroll
        for (int q = 0; q < 4; q++) { float v = s_x[t * CDIM + lane + q * 32]; s += v * v; }
        #pragma unroll
        for (int o = 16; o; o >>= 1) s += __shfl_xor_sync(0xffffffffu, s, o);
        if (lane == 0) s_sc[t] = rsqrtf(s * (1.f / (float)CDIM) + 1e-5f);
    }
    __syncthreads();
    float w = n1w[tid];
    #pragma unroll
    for (int t = 0; t < TT; t++)
        g_Xg[(size_t)(bk * TT + t) * CDIM + tid] = __float2bfloat16(s_x[t * CDIM + tid] * s_sc[t] * w);
}

// ---------------- HMMA GEMM: C[128-tile, 128-tile] = A[M,K] @ B[N,K]^T ----------------
// 256 threads = 8 warps (2 m x 4 n). EPI: 0=fp32 store, 1=rmsnorm2->bf16, 2=bias+gelu->bf16
#define KC 128
#define PD (KC + 8)
template <int KTOT, int EPI>
__global__ void __launch_bounds__(256) hgemm_k(
    const __nv_bfloat16* __restrict__ A, const __nv_bfloat16* __restrict__ Bm,
    float* __restrict__ C, int ldc,
    const float* __restrict__ ep, __nv_bfloat16* __restrict__ OutBf) {
    extern __shared__ char smraw[];
    __nv_bfloat16* sA = (__nv_bfloat16*)smraw;
    __nv_bfloat16* sB = sA + 128 * PD;
    int tid = threadIdx.x;
    int wid = tid >> 5, lane = tid & 31;
    int warp_m = wid & 1, warp_n = wid >> 1;
    int gId = lane >> 2, tig = lane & 3;
    int m0 = blockIdx.x * 128;
    int n0 = blockIdx.y * 128;

    float acc[4][4][4];
    #pragma unroll
    for (int i = 0; i < 4; i++)
        #pragma unroll
        for (int j = 0; j < 4; j++)
            { acc[i][j][0]=0.f; acc[i][j][1]=0.f; acc[i][j][2]=0.f; acc[i][j][3]=0.f; }

    const __nv_bfloat16* Ag = A + (size_t)m0 * KTOT;
    const __nv_bfloat16* Bg = Bm + (size_t)n0 * KTOT;

    #pragma unroll
    for (int kc = 0; kc < KTOT / KC; kc++) {
        // load tiles
        for (int i = tid; i < 128 * KC / 8; i += 256) {
            int m = i >> 4, k8 = (i & 15) * 8;
            *(uint4*)&sA[m * PD + k8] = *(const uint4*)&Ag[(size_t)m * KTOT + kc * KC + k8];
            *(uint4*)&sB[m * PD + k8] = *(const uint4*)&Bg[(size_t)m * KTOT + kc * KC + k8];
        }
        __syncthreads();
        #pragma unroll
        for (int ks = 0; ks < KC / 16; ks++) {
            int col = ks * 16 + tig * 2;
            uint32_t af[4][4], bf[4][2];
            #pragma unroll
            for (int mt = 0; mt < 4; mt++) {
                int r = warp_m * 64 + mt * 16 + gId;
                af[mt][0] = *(const uint32_t*)&sA[r * PD + col];
                af[mt][1] = *(const uint32_t*)&sA[(r + 8) * PD + col];
                af[mt][2] = *(const uint32_t*)&sA[r * PD + col + 8];
                af[mt][3] = *(const uint32_t*)&sA[(r + 8) * PD + col + 8];
            }
            #pragma unroll
            for (int nt = 0; nt < 4; nt++) {
                int r = warp_n * 32 + nt * 8 + gId;
                bf[nt][0] = *(const uint32_t*)&sB[r * PD + col];
                bf[nt][1] = *(const uint32_t*)&sB[r * PD + col + 8];
            }
            #pragma unroll
            for (int mt = 0; mt < 4; mt++)
                #pragma unroll
                for (int nt = 0; nt < 4; nt++)
                    mma_bf16(acc[mt][nt], af[mt], bf[nt]);
        }
        __syncthreads();
    }

    if (EPI == 0) {
        #pragma unroll
        for (int mt = 0; mt < 4; mt++) {
            int row = m0 + warp_m * 64 + mt * 16 + gId;
            #pragma unroll
            for (int nt = 0; nt < 4; nt++) {
                int col = n0 + warp_n * 32 + nt * 8 + tig * 2;
                *(float2*)&C[(size_t)row * ldc + col]       = make_float2(acc[mt][nt][0], acc[mt][nt][1]);
                *(float2*)&C[(size_t)(row + 8) * ldc + col] = make_float2(acc[mt][nt][2], acc[mt][nt][3]);
            }
        }
    } else if (EPI == 1) {
        // rmsnorm2 fused: stage fp32 tile in smem, per-row scale, write bf16
        float* sc = (float*)smraw;
        const int PDC = 132;
        #pragma unroll
        for (int mt = 0; mt < 4; mt++) {
            int lr = warp_m * 64 + mt * 16 + gId;
            #pragma unroll
            for (int nt = 0; nt < 4; nt++) {
                int lc = warp_n * 32 + nt * 8 + tig * 2;
                sc[lr * PDC + lc]           = acc[mt][nt][0];
                sc[lr * PDC + lc + 1]       = acc[mt][nt][1];
                sc[(lr + 8) * PDC + lc]     = acc[mt][nt][2];
                sc[(lr + 8) * PDC + lc + 1] = acc[mt][nt][3];
            }
        }
        __syncthreads();
        int r = tid >> 1, hf = tid & 1;
        const float* rowp = sc + r * PDC + hf * 64;
        float s = 0.f;
        #pragma unroll
        for (int j = 0; j < 16; j++) {
            float4 v = *(const float4*)(rowp + j * 4);
            s += v.x * v.x + v.y * v.y + v.z * v.z + v.w * v.w;
        }
        s += __shfl_xor_sync(0xffffffffu, s, 1);
        float scl = rsqrtf(s * (1.f / (float)CDIM) + 1e-5f);
        __nv_bfloat162* dst = (__nv_bfloat162*)(OutBf + (size_t)(m0 + r) * CDIM + hf * 64);
        #pragma unroll
        for (int j = 0; j < 16; j++) {
            float4 v = *(const float4*)(rowp + j * 4);
            float4 w = *(const float4*)&ep[hf * 64 + j * 4];
            dst[j * 2]     = __floats2bfloat162_rn(v.x * scl * w.x, v.y * scl * w.y);
            dst[j * 2 + 1] = __floats2bfloat162_rn(v.z * scl * w.z, v.w * scl * w.w);
        }
    } else {
        // bias + exact gelu fused -> bf16
        const float kq = 0.7071067811865475f;
        #pragma unroll
        for (int mt = 0; mt < 4; mt++) {
            int row = m0 + warp_m * 64 + mt * 16 + gId;
            #pragma unroll
            for (int nt = 0; nt < 4; nt++) {
                int col = warp_n * 32 + nt * 8 + tig * 2;
                float2 bb = *(const float2*)&ep[col];
                float x0 = acc[mt][nt][0] + bb.x, x1 = acc[mt][nt][1] + bb.y;
                float x2 = acc[mt][nt][2] + bb.x, x3 = acc[mt][nt][3] + bb.y;
                x0 = 0.5f * x0 * (1.f + erff(x0 * kq));
                x1 = 0.5f * x1 * (1.f + erff(x1 * kq));
                x2 = 0.5f * x2 * (1.f + erff(x2 * kq));
                x3 = 0.5f * x3 * (1.f + erff(x3 * kq));
                *(__nv_bfloat162*)&OutBf[(size_t)row * CDIM + col]       = __floats2bfloat162_rn(x0, x1);
                *(__nv_bfloat162*)&OutBf[(size_t)(row + 8) * CDIM + col] = __floats2bfloat162_rn(x2, x3);
            }
        }
    }
}

// ---------------- conv + x_proj + dt + scan + gate -> y bf16 ----------------
__global__ void __launch_bounds__(256) conv_scan_k(
    const float* __restrict__ conv_w, const float* __restrict__ conv_b,
    const float* __restrict__ dt_b,   const float* __restrict__ Dp) {
    extern __shared__ float smf[];
    float* s_xz  = smf;             // 16*512
    float* s_xc  = smf + 8192;      // 16*256
    float* s_dbl = smf + 12288;     // 16*48

    int bk = blockIdx.x;
    int tid = threadIdx.x;

    for (int i = tid; i < TT * 512; i += 256)
        s_xz[i] = g_xz[(size_t)bk * (TT * 512) + i];
    __syncthreads();

    int d = tid;
    {
        float w0 = conv_w[d * 4 + 0], w1 = conv_w[d * 4 + 1];
        float w2 = conv_w[d * 4 + 2], w3 = conv_w[d * 4 + 3];
        float cb = conv_b[d];
        #pragma unroll
        for (int t = 0; t < TT; t++) {
            float acc = cb;
            if (t >= 3) acc += w0 * s_xz[(t - 3) * 512 + d];
            if (t >= 2) acc += w1 * s_xz[(t - 2) * 512 + d];
            if (t >= 1) acc += w2 * s_xz[(t - 1) * 512 + d];
            acc += w3 * s_xz[t * 512 + d];
            s_xc[t * DI + d] = acc / (1.f + expf(-acc));
        }
    }
    __syncthreads();
    for (int i = tid; i < TT * DBL; i += 256) {
        int t = i / DBL, r = i % DBL;
        float acc = 0.f;
        #pragma unroll 4
        for (int dd = 0; dd < DI; dd++) acc += s_xc[t * DI + dd] * g_wT_xp[dd * DBL + r];
        s_dbl[t * 48 + r] = acc;
    }
    __syncthreads();
    {
        float bias = dt_b[d];
        float wdt[DTR];
        #pragma unroll
        for (int r = 0; r < DTR; r++) wdt[r] = g_wT_dt[r * DI + d];
        float a[DS], h[DS];
        #pragma unroll
        for (int s = 0; s < DS; s++) { a[s] = g_A[d * DS + s]; h[s] = 0.f; }
        float Dd = Dp[d];
        #pragma unroll
        for (int t = 0; t < TT; t++) {
            float acc = bias;
            #pragma unroll
            for (int r = 0; r < DTR; r++) acc += s_dbl[t * 48 + r] * wdt[r];
            float dtv = (acc > 20.f) ? acc : log1pf(expf(acc));
            float xv  = s_xc[t * DI + d];
            float dtx = dtv * xv;
            float y = 0.f;
            #pragma unroll
            for (int s = 0; s < DS; s++) {
                float dA = __expf(dtv * a[s]);
                h[s] = dA * h[s] + dtx * s_dbl[t * 48 + 8 + s];
                y += h[s] * s_dbl[t * 48 + 24 + s];
            }
            y += xv * Dd;
            float zv = s_xz[t * 512 + DI + d];
            y *= zv / (1.f + expf(-zv));
            g_ybf[(size_t)(bk * TT + t) * DI + d] = __float2bfloat16(y);
        }
    }
}

// ---------------- final combine: out = x_in + scatter(G2 + b2) ----------------
__global__ void out_k(const float* __restrict__ x_in, const float* __restrict__ b2,
                      float* __restrict__ out) {
    int gid = blockIdx.x * 256 + threadIdx.x;
    size_t base = (size_t)gid * 4;
    int n = (int)(base % NPIX);
    size_t rest = base / NPIX;
    int c = (int)(rest % CDIM); rest /= CDIM;
    int t = (int)(rest % TT);
    int b = (int)(rest / TT);
    float4 v = *(const float4*)&x_in[base];
    int ib = b * NPIX + n;
    int k0 = g_inv[ib], k1 = g_inv[ib + 1], k2 = g_inv[ib + 2], k3 = g_inv[ib + 3];
    float bc = b2[c];
    const float* G2 = g_xz;   // reuse
    size_t rb = ((size_t)b * KKEEP) * TT;
    if (k0 >= 0) v.x += G2[(rb + (size_t)k0 * TT + t) * CDIM + c] + bc;
    if (k1 >= 0) v.y += G2[(rb + (size_t)k1 * TT + t) * CDIM + c] + bc;
    if (k2 >= 0) v.z += G2[(rb + (size_t)k2 * TT + t) * CDIM + c] + bc;
    if (k3 >= 0) v.w += G2[(rb + (size_t)k3 * TT + t) * CDIM + c] + bc;
    *(float4*)&out[base] = v;
}

// ---------------- launch ----------------
extern "C" void kernel_launch(void* const* d_in, const int* in_sizes, int n_in,
                              void* d_out, int out_size) {
    const float* x_in    = (const float*)d_in[0];
    const float* norm1_w = (const float*)d_in[1];
    const float* norm2_w = (const float*)d_in[2];
    const float* in_w    = (const float*)d_in[3];
    const float* conv_w  = (const float*)d_in[4];
    const float* conv_b  = (const float*)d_in[5];
    const float* xp_w    = (const float*)d_in[6];
    const float* dt_w    = (const float*)d_in[7];
    const float* dt_b    = (const float*)d_in[8];
    const float* A_log   = (const float*)d_in[9];
    const float* Dp      = (const float*)d_in[10];
    const float* out_w   = (const float*)d_in[11];
    const float* m1      = (const float*)d_in[12];
    const float* b1      = (const float*)d_in[13];
    const float* m2      = (const float*)d_in[14];
    const float* b2      = (const float*)d_in[15];
    float* out = (float*)d_out;

    void *pXg, *pWin, *pWout, *pM1, *pM2, *pXz, *pYbf, *pH0, *pH1;
    cudaGetSymbolAddress(&pXg,  g_Xg);
    cudaGetSymbolAddress(&pWin, g_bWin);
    cudaGetSymbolAddress(&pWout,g_bWout);
    cudaGetSymbolAddress(&pM1,  g_bM1);
    cudaGetSymbolAddress(&pM2,  g_bM2);
    cudaGetSymbolAddress(&pXz,  g_xz);
    cudaGetSymbolAddress(&pYbf, g_ybf);
    cudaGetSymbolAddress(&pH0,  g_h0);
    cudaGetSymbolAddress(&pH1,  g_h1);

    const int smemG = 2 * 128 * PD * 2;   // 69632 B
    cudaFuncSetAttribute(hgemm_k<128, 0>, cudaFuncAttributeMaxDynamicSharedMemorySize, smemG);
    cudaFuncSetAttribute(hgemm_k<256, 1>, cudaFuncAttributeMaxDynamicSharedMemorySize, smemG);
    cudaFuncSetAttribute(hgemm_k<128, 2>, cudaFuncAttributeMaxDynamicSharedMemorySize, smemG);
    cudaFuncSetAttribute(conv_scan_k,     cudaFuncAttributeMaxDynamicSharedMemorySize, 52224);

    prep_k<<<64, 256>>>(in_w, out_w, xp_w, dt_w, m1, m2, A_log);
    energy_k<<<BB * (NPIX / 32), 256>>>(x_in);
    rank_k<<<BB * NPIX / 256, 256>>>();
    compact_k<<<BB, 256>>>();
    gather_norm_k<<<BB * KKEEP, 128>>>(x_in, norm1_w);

    // in_proj: [36864,128] @ [512,128]^T -> g_xz [36864,512]
    hgemm_k<128, 0><<<dim3(ROWS / 128, 4), 256, smemG>>>(
        (const __nv_bfloat16*)pXg, (const __nv_bfloat16*)pWin, (float*)pXz, 512, nullptr, nullptr);
    conv_scan_k<<<BB * KKEEP, 256, 52224>>>(conv_w, conv_b, dt_b, Dp);
    // out_proj + fused rmsnorm2: [36864,256] @ [128,256]^T -> g_h0 bf16
    hgemm_k<256, 1><<<dim3(ROWS / 128, 1), 256, smemG>>>(
        (const __nv_bfloat16*)pYbf, (const __nv_bfloat16*)pWout, nullptr, 0, norm2_w, (__nv_bfloat16*)pH0);
    // mix1 + fused bias/gelu -> g_h1 bf16
    hgemm_k<128, 2><<<dim3(ROWS / 128, 1), 256, smemG>>>(
        (const __nv_bfloat16*)pH0, (const __nv_bfloat16*)pM1, nullptr, 0, b1, (__nv_bfloat16*)pH1);
    // mix2 -> g_xz (G2, fp32)
    hgemm_k<128, 0><<<dim3(ROWS / 128, 1), 256, smemG>>>(
        (const __nv_bfloat16*)pH1, (const __nv_bfloat16*)pM2, (float*)pXz, 128, nullptr, nullptr);
    out_k<<<(BB * TT * CDIM * NPIX) / 4 / 256, 256>>>(x_in, b2, out);
}